// round 10
// baseline (speedup 1.0000x reference)
#include <cuda_runtime.h>
#include <cuda_fp16.h>
#include <cstdint>
#include <math.h>

#define BATCH 4
#define SEQ   2048
#define DIM   1024
#define MTOT  (BATCH*SEQ)

// Scratch (__device__ globals; allocation-free rule)
__device__ __half g_QKV[(size_t)MTOT*3*DIM];    // 48 MB ([8192][3072]: Q|K|V fp16)
__device__ __half g_VT [(size_t)BATCH*SEQ*DIM]; // 16 MB (V^T per batch: [D][S])
__device__ __half g_Ph [(size_t)BATCH*SEQ*SEQ]; // 32 MB (exp(scores) fp16, masked)
__device__ float  g_RS [MTOT];                  // row sums of exp(scores)
__device__ __half g_X  [(size_t)MTOT*DIM];      // 16 MB (x fp16)
__device__ __half g_W  [(size_t)3*DIM*DIM];     //  6 MB (Wq|Wk|Wv fp16, row-concat)
__device__ float  g_B  [3*DIM];                 // packed bias (f32)

// ---------------------------------------------------------------------------
__device__ __forceinline__ uint32_t smem_u32(const void* p){
    uint32_t a;
    asm("{ .reg .u64 t; cvta.to.shared.u64 t, %1; cvt.u32.u64 %0, t; }"
        : "=r"(a) : "l"(p));
    return a;
}
#define SW128(o) ((o) ^ (((o) >> 3) & 0x70))

__device__ __forceinline__ void cp16(uint32_t s, const void* g){
    asm volatile("cp.async.cg.shared.global [%0], [%1], 16;" :: "r"(s), "l"(g));
}

// ---------------------------------------------------------------------------
__global__ __launch_bounds__(256)
void to_half(const float* __restrict__ src, __half* __restrict__ dst, int n4)
{
    int i = blockIdx.x * 256 + threadIdx.x;
    if (i >= n4) return;
    float4 v = ((const float4*)src)[i];
    ((__half2*)dst)[i*2]   = __floats2half2_rn(v.x, v.y);
    ((__half2*)dst)[i*2+1] = __floats2half2_rn(v.z, v.w);
}

// pack bias + zero row sums, one launch (grid covers MTOT)
__global__ __launch_bounds__(256)
void prep_aux(const float* __restrict__ bq, const float* __restrict__ bk,
              const float* __restrict__ bv, float* __restrict__ b,
              float* __restrict__ rs)
{
    int i = blockIdx.x * 256 + threadIdx.x;
    if (i < DIM){ b[i] = bq[i]; b[DIM + i] = bk[i]; b[2*DIM + i] = bv[i]; }
    if (i < MTOT) rs[i] = 0.f;
}

// ---------------------------------------------------------------------------
// fp16 HMMA GEMM-NT, CTA tile 128x128, BK=64, 3-stage cp.async (2 in flight),
// one __syncthreads per chunk. 8 warps (4M x 2N), warp tile 32x64.
// mode 0: C fp16 = acc + bias (QKV)
// mode 1: Ph fp16 = causal-masked __expf(acc*scale); atomic rowsum (skip bx>by)
// mode 2: C f32 = acc / rowsum[row]; K truncated at (by+1)*128
// ---------------------------------------------------------------------------
#define STG 32768u

__global__ __launch_bounds__(256, 2)
void gemm_h(const __half* __restrict__ A, const __half* __restrict__ B,
            const float* __restrict__ bias, float* __restrict__ rowsum,
            void* __restrict__ Cv,
            int K, int lda, int ldb, int ldc,
            long sA, long sB, long sC, float scale, int mode)
{
    const int bx = blockIdx.x, by = blockIdx.y, bz = blockIdx.z;
    if (mode == 1 && bx > by) return;
    A += (size_t)bz * sA; B += (size_t)bz * sB;

    const int Keff = (mode == 2) ? min(K, (by + 1) * 128) : K;
    const int nch  = Keff >> 6;

    extern __shared__ char dsm[];
    const uint32_t base = (smem_u32(dsm) + 1023) & ~1023u;
    const int tid = threadIdx.x, lane = tid & 31, wid = tid >> 5;
    const int wm = wid & 3, wn = wid >> 2;

    // per-warp n-tile skip mask (mode-1 diagonal CTAs: tiles fully above diag)
    uint32_t skipmask = 0;
    if (mode == 1 && bx == by){
        #pragma unroll
        for (int nt = 0; nt < 8; nt++)
            if (wn * 64 + nt * 8 > wm * 32 + 31) skipmask |= 1u << nt;
    }

    const __half* Ab = A + (size_t)(by * 128) * lda;
    const __half* Bb = B + (size_t)(bx * 128) * ldb;

    auto load_tile = [&](const __half* gb, int ld, int k0, uint32_t sbase){
        #pragma unroll
        for (int it = 0; it < 4; it++){
            int idx = tid + it * 256;
            int r = idx >> 3, c8 = idx & 7;
            uint32_t off = (uint32_t)(r * 128 + c8 * 16);
            cp16(sbase + SW128(off), gb + (size_t)r * ld + k0 + c8 * 8);
        }
    };

    const uint32_t offA = (uint32_t)((wm*32 + (lane & 15)) * 128 + (lane >> 4) * 16);
    uint32_t offB[4];
    #pragma unroll
    for (int g = 0; g < 4; g++)
        offB[g] = (uint32_t)((wn*64 + g*16 + (lane & 7) + ((lane >> 4) & 1) * 8) * 128
                             + ((lane >> 3) & 1) * 16);

    float acc[2][8][4];
    #pragma unroll
    for (int mt = 0; mt < 2; mt++)
        #pragma unroll
        for (int nt = 0; nt < 8; nt++)
            #pragma unroll
            for (int j = 0; j < 4; j++) acc[mt][nt][j] = 0.f;

    // prologue: chunks 0,1 into stages 0,1
    load_tile(Ab, lda, 0, base);
    load_tile(Bb, ldb, 0, base + 16384);
    asm volatile("cp.async.commit_group;");
    if (nch > 1){
        load_tile(Ab, lda, 64, base + STG);
        load_tile(Bb, ldb, 64, base + STG + 16384);
    }
    asm volatile("cp.async.commit_group;");

    for (int i = 0; i < nch; i++){
        asm volatile("cp.async.wait_group 1;");
        __syncthreads();
        {
            int s = i + 2;
            if (s < nch){
                uint32_t sb = base + (uint32_t)(s % 3) * STG;
                load_tile(Ab, lda, s * 64, sb);
                load_tile(Bb, ldb, s * 64, sb + 16384);
            }
            asm volatile("cp.async.commit_group;");
        }
        const uint32_t ab = base + (uint32_t)(i % 3) * STG;
        const uint32_t bb = ab + 16384;

        #pragma unroll
        for (int ks = 0; ks < 4; ks++){
            const uint32_t kadd = ks * 32;
            uint32_t ar[2][4];
            #pragma unroll
            for (int mt = 0; mt < 2; mt++){
                uint32_t ad = ab + SW128(offA + (uint32_t)mt * 2048 + kadd);
                asm volatile(
                    "ldmatrix.sync.aligned.m8n8.x4.shared.b16 {%0,%1,%2,%3}, [%4];"
                    : "=r"(ar[mt][0]), "=r"(ar[mt][1]),
                      "=r"(ar[mt][2]), "=r"(ar[mt][3]) : "r"(ad));
            }
            // two halves: 2 LDSM.x4 + 8 MMA each (shorter dep chains)
            #pragma unroll
            for (int half = 0; half < 2; half++){
                uint32_t br[4][2];
                #pragma unroll
                for (int g = 0; g < 2; g++){
                    int gg = half * 2 + g;
                    if (((skipmask >> (2*gg)) & 3u) != 3u){
                        uint32_t ad = bb + SW128(offB[gg] + kadd);
                        asm volatile(
                            "ldmatrix.sync.aligned.m8n8.x4.shared.b16 {%0,%1,%2,%3}, [%4];"
                            : "=r"(br[2*g][0]), "=r"(br[2*g][1]),
                              "=r"(br[2*g+1][0]), "=r"(br[2*g+1][1]) : "r"(ad));
                    }
                }
                #pragma unroll
                for (int ntl = 0; ntl < 4; ntl++){
                    int nt = half * 4 + ntl;
                    if ((skipmask >> nt) & 1u) continue;
                    #pragma unroll
                    for (int mt = 0; mt < 2; mt++){
                        asm volatile(
                            "mma.sync.aligned.m16n8k16.row.col.f32.f16.f16.f32 "
                            "{%0,%1,%2,%3}, {%4,%5,%6,%7}, {%8,%9}, {%0,%1,%2,%3};"
                            : "+f"(acc[mt][nt][0]), "+f"(acc[mt][nt][1]),
                              "+f"(acc[mt][nt][2]), "+f"(acc[mt][nt][3])
                            : "r"(ar[mt][0]), "r"(ar[mt][1]),
                              "r"(ar[mt][2]), "r"(ar[mt][3]),
                              "r"(br[ntl][0]), "r"(br[ntl][1]));
                    }
                }
            }
        }
    }

    // ---------------- epilogue ----------------
    const int r0 = lane >> 2, c0 = (lane & 3) * 2;

    if (mode == 0){
        __half* C = (__half*)Cv + (size_t)bz * sC;
        #pragma unroll
        for (int mt = 0; mt < 2; mt++){
            const int mrow = by * 128 + wm * 32 + mt * 16 + r0;
            #pragma unroll
            for (int nt = 0; nt < 8; nt++){
                const int col = bx * 128 + wn * 64 + nt * 8 + c0;
                float b0 = bias[col], b1 = bias[col + 1];
                *(__half2*)(C + (size_t)mrow * ldc + col) =
                    __floats2half2_rn(acc[mt][nt][0] + b0, acc[mt][nt][1] + b1);
                *(__half2*)(C + (size_t)(mrow + 8) * ldc + col) =
                    __floats2half2_rn(acc[mt][nt][2] + b0, acc[mt][nt][3] + b1);
            }
        }
    } else if (mode == 1){
        __half* C = (__half*)Cv + (size_t)bz * sC;
        float rs[2][2] = {{0.f, 0.f}, {0.f, 0.f}};
        #pragma unroll
        for (int mt = 0; mt < 2; mt++){
            const int q0 = by * 128 + wm * 32 + mt * 16 + r0;
            const int q1 = q0 + 8;
            #pragma unroll
            for (int nt = 0; nt < 8; nt++){
                const int col = bx * 128 + wn * 64 + nt * 8 + c0;
                float e0 = (col     <= q0) ? __expf(acc[mt][nt][0] * scale) : 0.f;
                float e1 = (col + 1 <= q0) ? __expf(acc[mt][nt][1] * scale) : 0.f;
                float e2 = (col     <= q1) ? __expf(acc[mt][nt][2] * scale) : 0.f;
                float e3 = (col + 1 <= q1) ? __expf(acc[mt][nt][3] * scale) : 0.f;
                rs[mt][0] += e0 + e1;
                rs[mt][1] += e2 + e3;
                *(__half2*)(C + (size_t)q0 * ldc + col) = __floats2half2_rn(e0, e1);
                *(__half2*)(C + (size_t)q1 * ldc + col) = __floats2half2_rn(e2, e3);
            }
        }
        #pragma unroll
        for (int mt = 0; mt < 2; mt++)
            #pragma unroll
            for (int h = 0; h < 2; h++){
                float v = rs[mt][h];
                v += __shfl_xor_sync(0xffffffffu, v, 1);
                v += __shfl_xor_sync(0xffffffffu, v, 2);
                if ((lane & 3) == 0){
                    int q = by * 128 + wm * 32 + mt * 16 + r0 + h * 8;
                    atomicAdd(rowsum + bz * SEQ + q, v);
                }
            }
    } else {
        float* C = (float*)Cv + (size_t)bz * sC;
        #pragma unroll
        for (int mt = 0; mt < 2; mt++){
            const int mrow = by * 128 + wm * 32 + mt * 16 + r0;
            const float i0 = 1.0f / rowsum[bz * SEQ + mrow];
            const float i1 = 1.0f / rowsum[bz * SEQ + mrow + 8];
            #pragma unroll
            for (int nt = 0; nt < 8; nt++){
                const int col = bx * 128 + wn * 64 + nt * 8 + c0;
                *(float2*)(C + (size_t)mrow * ldc + col) =
                    make_float2(acc[mt][nt][0] * i0, acc[mt][nt][1] * i0);
                *(float2*)(C + (size_t)(mrow + 8) * ldc + col) =
                    make_float2(acc[mt][nt][2] * i1, acc[mt][nt][3] * i1);
            }
        }
    }
}

// ---------------------------------------------------------------------------
__global__ __launch_bounds__(256)
void transpose_sd(const __half* __restrict__ V, __half* __restrict__ VT, int ldv)
{
    __shared__ __half t[32][33];
    const int b  = blockIdx.z;
    const int s0 = blockIdx.x * 32, d0 = blockIdx.y * 32;
    const __half* Vb = V  + (size_t)b * SEQ * ldv;
    __half* VTb      = VT + (size_t)b * SEQ * DIM;
    const int x = threadIdx.x, y = threadIdx.y;   // 32 x 8
    #pragma unroll
    for (int i = 0; i < 32; i += 8)
        t[y + i][x] = Vb[(size_t)(s0 + y + i) * ldv + d0 + x];
    __syncthreads();
    #pragma unroll
    for (int i = 0; i < 32; i += 8)
        VTb[(size_t)(d0 + y + i) * SEQ + s0 + x] = t[x][y + i];
}

// ---------------------------------------------------------------------------
extern "C" void kernel_launch(void* const* d_in, const int* in_sizes, int n_in,
                              void* d_out, int out_size)
{
    const float* x  = (const float*)d_in[0];
    const float* Wq = (const float*)d_in[1];
    const float* bq = (const float*)d_in[2];
    const float* Wk = (const float*)d_in[3];
    const float* bk = (const float*)d_in[4];
    const float* Wv = (const float*)d_in[5];
    const float* bv = (const float*)d_in[6];
    float* out = (float*)d_out;

    __half *QKV, *VT, *Ph, *X, *W;
    float *RS, *Bc;
    cudaGetSymbolAddress((void**)&QKV, g_QKV);
    cudaGetSymbolAddress((void**)&VT,  g_VT);
    cudaGetSymbolAddress((void**)&Ph,  g_Ph);
    cudaGetSymbolAddress((void**)&RS,  g_RS);
    cudaGetSymbolAddress((void**)&X,   g_X);
    cudaGetSymbolAddress((void**)&W,   g_W);
    cudaGetSymbolAddress((void**)&Bc,  g_B);

    const size_t SHM = 3 * STG + 1024;           // 99,328 B
    static bool attr_set = false;
    if (!attr_set){
        cudaFuncSetAttribute(gemm_h, cudaFuncAttributeMaxDynamicSharedMemorySize, (int)SHM);
        attr_set = true;
    }

    const long SD = (long)SEQ * DIM;
    const long SS = (long)SEQ * SEQ;
    const int  DD = DIM * DIM;
    const int  LQKV = 3 * DIM;
    dim3 t(256);

    to_half<<<(MTOT*DIM/4 + 255)/256, 256>>>(x,  X,        MTOT*DIM/4);
    to_half<<<(DD/4 + 255)/256, 256>>>(Wq, W,            DD/4);
    to_half<<<(DD/4 + 255)/256, 256>>>(Wk, W + DD,       DD/4);
    to_half<<<(DD/4 + 255)/256, 256>>>(Wv, W + 2*DD,     DD/4);
    prep_aux<<<(MTOT + 255)/256, 256>>>(bq, bk, bv, Bc, RS);

    // Fused QKV projection: [8192,3072] = X @ [Wq;Wk;Wv]^T + b -> fp16
    dim3 gq(LQKV / 128, MTOT / 128, 1);
    gemm_h<<<gq, t, SHM>>>(X, W, Bc, nullptr, QKV, DIM, DIM, DIM, LQKV,
                           0, 0, 0, 1.0f, 0);

    // VT[b][d][s] = V[b][s][d]
    transpose_sd<<<dim3(SEQ/32, DIM/32, BATCH), dim3(32, 8)>>>(QKV + 2*DIM, VT, LQKV);

    // Ph = exp(Q K^T / 32) masked + atomic row sums; lower-triangle blocks only
    dim3 gs(SEQ / 128, SEQ / 128, BATCH);
    gemm_h<<<gs, t, SHM>>>(QKV, QKV + DIM, nullptr, RS, Ph, DIM, LQKV, LQKV, SEQ,
                           (long)SEQ * LQKV, (long)SEQ * LQKV, SS, 0.03125f, 1);

    // out = (Ph @ V) / rowsum -> f32; K truncated at causal boundary
    dim3 go(DIM / 128, SEQ / 128, BATCH);
    gemm_h<<<go, t, SHM>>>(Ph, VT, nullptr, RS, out, SEQ, SEQ, SEQ, DIM,
                           SS, SD, SD, 1.0f, 2);
}

// round 13
// speedup vs baseline: 1.2746x; 1.2746x over previous
#include <cuda_runtime.h>
#include <cuda_fp16.h>
#include <cstdint>
#include <math.h>

#define BATCH 4
#define SEQ   2048
#define DIM   1024
#define MTOT  (BATCH*SEQ)

// Scratch (__device__ globals; allocation-free rule)
__device__ __half g_QKV[(size_t)MTOT*3*DIM];    // 48 MB ([8192][3072]: Q|K|V fp16)
__device__ __half g_VT [(size_t)BATCH*SEQ*DIM]; // 16 MB (V^T per batch: [D][S])
__device__ __half g_Ph [(size_t)BATCH*SEQ*SEQ]; // 32 MB (exp(scores) fp16, masked)
__device__ float  g_RS [MTOT];                  // row sums of exp(scores)
__device__ __half g_X  [(size_t)MTOT*DIM];      // 16 MB (x fp16)
__device__ __half g_W  [(size_t)3*DIM*DIM];     //  6 MB (Wq|Wk|Wv fp16, row-concat)
__device__ float  g_B  [3*DIM];                 // packed bias (f32)

// ---------------------------------------------------------------------------
__device__ __forceinline__ uint32_t smem_u32(const void* p){
    uint32_t a;
    asm("{ .reg .u64 t; cvta.to.shared.u64 t, %1; cvt.u32.u64 %0, t; }"
        : "=r"(a) : "l"(p));
    return a;
}
#define SW128(o) ((o) ^ (((o) >> 3) & 0x70))

__device__ __forceinline__ void cp16(uint32_t s, const void* g){
    asm volatile("cp.async.cg.shared.global [%0], [%1], 16;" :: "r"(s), "l"(g));
}

// ---------------------------------------------------------------------------
__global__ __launch_bounds__(256)
void to_half(const float* __restrict__ src, __half* __restrict__ dst, int n4)
{
    int i = blockIdx.x * 256 + threadIdx.x;
    if (i >= n4) return;
    float4 v = ((const float4*)src)[i];
    ((__half2*)dst)[i*2]   = __floats2half2_rn(v.x, v.y);
    ((__half2*)dst)[i*2+1] = __floats2half2_rn(v.z, v.w);
}

// pack bias + zero row sums, one launch (grid covers MTOT)
__global__ __launch_bounds__(256)
void prep_aux(const float* __restrict__ bq, const float* __restrict__ bk,
              const float* __restrict__ bv, float* __restrict__ b,
              float* __restrict__ rs)
{
    int i = blockIdx.x * 256 + threadIdx.x;
    if (i < DIM){ b[i] = bq[i]; b[DIM + i] = bk[i]; b[2*DIM + i] = bv[i]; }
    if (i < MTOT) rs[i] = 0.f;
}

// ---------------------------------------------------------------------------
// fp16 HMMA GEMM-NT, CTA tile 128x128, BK=64, 3-stage cp.async (2 in flight),
// ONE __syncthreads per chunk. 8 warps (4M x 2N), warp tile 32x64.
// mode 0: C fp16 = acc + bias (QKV)
// mode 1: Ph fp16 = causal-masked __expf(acc*scale); atomic rowsum (skip bx>by)
// mode 2: C f32 = acc / rowsum[row]; K truncated at (by+1)*128
// ---------------------------------------------------------------------------
#define STG 32768u

__global__ __launch_bounds__(256, 2)
void gemm_h(const __half* __restrict__ A, const __half* __restrict__ B,
            const float* __restrict__ bias, float* __restrict__ rowsum,
            void* __restrict__ Cv,
            int K, int lda, int ldb, int ldc,
            long sA, long sB, long sC, float scale, int mode)
{
    const int bx = blockIdx.x, by = blockIdx.y, bz = blockIdx.z;
    if (mode == 1 && bx > by) return;
    A += (size_t)bz * sA; B += (size_t)bz * sB;

    const int Keff = (mode == 2) ? min(K, (by + 1) * 128) : K;
    const int nch  = Keff >> 6;

    extern __shared__ char dsm[];
    const uint32_t base = (smem_u32(dsm) + 1023) & ~1023u;
    const int tid = threadIdx.x, lane = tid & 31, wid = tid >> 5;
    const int wm = wid & 3, wn = wid >> 2;

    const __half* Ab = A + (size_t)(by * 128) * lda;
    const __half* Bb = B + (size_t)(bx * 128) * ldb;

    // tile: 128 rows x 64 fp16 (128B rows), SW128, 16KB each (A then B)
    auto load_tile = [&](const __half* gb, int ld, int k0, uint32_t sbase){
        #pragma unroll
        for (int it = 0; it < 4; it++){
            int idx = tid + it * 256;
            int r = idx >> 3, c8 = idx & 7;
            uint32_t off = (uint32_t)(r * 128 + c8 * 16);
            cp16(sbase + SW128(off), gb + (size_t)r * ld + k0 + c8 * 8);
        }
    };

    const uint32_t offA = (uint32_t)((wm*32 + (lane & 15)) * 128 + (lane >> 4) * 16);
    uint32_t offB[4];
    #pragma unroll
    for (int g = 0; g < 4; g++)
        offB[g] = (uint32_t)((wn*64 + g*16 + (lane & 7) + ((lane >> 4) & 1) * 8) * 128
                             + ((lane >> 3) & 1) * 16);

    float acc[2][8][4];
    #pragma unroll
    for (int mt = 0; mt < 2; mt++)
        #pragma unroll
        for (int nt = 0; nt < 8; nt++)
            #pragma unroll
            for (int j = 0; j < 4; j++) acc[mt][nt][j] = 0.f;

    // prologue: chunks 0,1 into stages 0,1 (2 in flight)
    load_tile(Ab, lda, 0, base);
    load_tile(Bb, ldb, 0, base + 16384);
    asm volatile("cp.async.commit_group;");
    if (nch > 1){
        load_tile(Ab, lda, 64, base + STG);
        load_tile(Bb, ldb, 64, base + STG + 16384);
    }
    asm volatile("cp.async.commit_group;");

    for (int i = 0; i < nch; i++){
        asm volatile("cp.async.wait_group 1;");
        __syncthreads();                         // chunk i ready; i-1 fully consumed
        // issue chunk i+2 into stage (i+2)%3
        {
            int s = i + 2;
            if (s < nch){
                uint32_t sb = base + (uint32_t)(s % 3) * STG;
                load_tile(Ab, lda, s * 64, sb);
                load_tile(Bb, ldb, s * 64, sb + 16384);
            }
            asm volatile("cp.async.commit_group;");
        }
        const uint32_t ab = base + (uint32_t)(i % 3) * STG;
        const uint32_t bb = ab + 16384;

        #pragma unroll
        for (int ks = 0; ks < 4; ks++){
            const uint32_t kadd = ks * 32;
            uint32_t ar[2][4];
            #pragma unroll
            for (int mt = 0; mt < 2; mt++){
                uint32_t ad = ab + SW128(offA + (uint32_t)mt * 2048 + kadd);
                asm volatile(
                    "ldmatrix.sync.aligned.m8n8.x4.shared.b16 {%0,%1,%2,%3}, [%4];"
                    : "=r"(ar[mt][0]), "=r"(ar[mt][1]),
                      "=r"(ar[mt][2]), "=r"(ar[mt][3]) : "r"(ad));
            }
            uint32_t br[8][2];
            #pragma unroll
            for (int g = 0; g < 4; g++){
                uint32_t ad = bb + SW128(offB[g] + kadd);
                asm volatile(
                    "ldmatrix.sync.aligned.m8n8.x4.shared.b16 {%0,%1,%2,%3}, [%4];"
                    : "=r"(br[2*g][0]), "=r"(br[2*g][1]),
                      "=r"(br[2*g+1][0]), "=r"(br[2*g+1][1]) : "r"(ad));
            }
            #pragma unroll
            for (int mt = 0; mt < 2; mt++)
                #pragma unroll
                for (int nt = 0; nt < 8; nt++){
                    asm volatile(
                        "mma.sync.aligned.m16n8k16.row.col.f32.f16.f16.f32 "
                        "{%0,%1,%2,%3}, {%4,%5,%6,%7}, {%8,%9}, {%0,%1,%2,%3};"
                        : "+f"(acc[mt][nt][0]), "+f"(acc[mt][nt][1]),
                          "+f"(acc[mt][nt][2]), "+f"(acc[mt][nt][3])
                        : "r"(ar[mt][0]), "r"(ar[mt][1]),
                          "r"(ar[mt][2]), "r"(ar[mt][3]),
                          "r"(br[nt][0]), "r"(br[nt][1]));
                }
        }
    }

    // ---------------- epilogue ----------------
    const int r0 = lane >> 2, c0 = (lane & 3) * 2;

    if (mode == 0){
        __half* C = (__half*)Cv + (size_t)bz * sC;
        #pragma unroll
        for (int mt = 0; mt < 2; mt++){
            const int mrow = by * 128 + wm * 32 + mt * 16 + r0;
            #pragma unroll
            for (int nt = 0; nt < 8; nt++){
                const int col = bx * 128 + wn * 64 + nt * 8 + c0;
                float b0 = bias[col], b1 = bias[col + 1];
                *(__half2*)(C + (size_t)mrow * ldc + col) =
                    __floats2half2_rn(acc[mt][nt][0] + b0, acc[mt][nt][1] + b1);
                *(__half2*)(C + (size_t)(mrow + 8) * ldc + col) =
                    __floats2half2_rn(acc[mt][nt][2] + b0, acc[mt][nt][3] + b1);
            }
        }
    } else if (mode == 1){
        __half* C = (__half*)Cv + (size_t)bz * sC;
        float rs[2][2] = {{0.f, 0.f}, {0.f, 0.f}};
        #pragma unroll
        for (int mt = 0; mt < 2; mt++){
            const int q0 = by * 128 + wm * 32 + mt * 16 + r0;
            const int q1 = q0 + 8;
            #pragma unroll
            for (int nt = 0; nt < 8; nt++){
                const int col = bx * 128 + wn * 64 + nt * 8 + c0;
                float e0 = (col     <= q0) ? __expf(acc[mt][nt][0] * scale) : 0.f;
                float e1 = (col + 1 <= q0) ? __expf(acc[mt][nt][1] * scale) : 0.f;
                float e2 = (col     <= q1) ? __expf(acc[mt][nt][2] * scale) : 0.f;
                float e3 = (col + 1 <= q1) ? __expf(acc[mt][nt][3] * scale) : 0.f;
                rs[mt][0] += e0 + e1;
                rs[mt][1] += e2 + e3;
                *(__half2*)(C + (size_t)q0 * ldc + col) = __floats2half2_rn(e0, e1);
                *(__half2*)(C + (size_t)q1 * ldc + col) = __floats2half2_rn(e2, e3);
            }
        }
        // reduce across the 4 lanes sharing each row
        #pragma unroll
        for (int mt = 0; mt < 2; mt++)
            #pragma unroll
            for (int h = 0; h < 2; h++){
                float v = rs[mt][h];
                v += __shfl_xor_sync(0xffffffffu, v, 1);
                v += __shfl_xor_sync(0xffffffffu, v, 2);
                if ((lane & 3) == 0){
                    int q = by * 128 + wm * 32 + mt * 16 + r0 + h * 8;
                    atomicAdd(rowsum + bz * SEQ + q, v);
                }
            }
    } else {
        float* C = (float*)Cv + (size_t)bz * sC;
        #pragma unroll
        for (int mt = 0; mt < 2; mt++){
            const int mrow = by * 128 + wm * 32 + mt * 16 + r0;
            const float i0 = 1.0f / rowsum[bz * SEQ + mrow];
            const float i1 = 1.0f / rowsum[bz * SEQ + mrow + 8];
            #pragma unroll
            for (int nt = 0; nt < 8; nt++){
                const int col = bx * 128 + wn * 64 + nt * 8 + c0;
                *(float2*)(C + (size_t)mrow * ldc + col) =
                    make_float2(acc[mt][nt][0] * i0, acc[mt][nt][1] * i0);
                *(float2*)(C + (size_t)(mrow + 8) * ldc + col) =
                    make_float2(acc[mt][nt][2] * i1, acc[mt][nt][3] * i1);
            }
        }
    }
}

// ---------------------------------------------------------------------------
__global__ __launch_bounds__(256)
void transpose_sd(const __half* __restrict__ V, __half* __restrict__ VT, int ldv)
{
    __shared__ __half t[32][33];
    const int b  = blockIdx.z;
    const int s0 = blockIdx.x * 32, d0 = blockIdx.y * 32;
    const __half* Vb = V  + (size_t)b * SEQ * ldv;
    __half* VTb      = VT + (size_t)b * SEQ * DIM;
    const int x = threadIdx.x, y = threadIdx.y;   // 32 x 8
    #pragma unroll
    for (int i = 0; i < 32; i += 8)
        t[y + i][x] = Vb[(size_t)(s0 + y + i) * ldv + d0 + x];
    __syncthreads();
    #pragma unroll
    for (int i = 0; i < 32; i += 8)
        VTb[(size_t)(d0 + y + i) * SEQ + s0 + x] = t[x][y + i];
}

// ---------------------------------------------------------------------------
extern "C" void kernel_launch(void* const* d_in, const int* in_sizes, int n_in,
                              void* d_out, int out_size)
{
    const float* x  = (const float*)d_in[0];
    const float* Wq = (const float*)d_in[1];
    const float* bq = (const float*)d_in[2];
    const float* Wk = (const float*)d_in[3];
    const float* bk = (const float*)d_in[4];
    const float* Wv = (const float*)d_in[5];
    const float* bv = (const float*)d_in[6];
    float* out = (float*)d_out;

    __half *QKV, *VT, *Ph, *X, *W;
    float *RS, *Bc;
    cudaGetSymbolAddress((void**)&QKV, g_QKV);
    cudaGetSymbolAddress((void**)&VT,  g_VT);
    cudaGetSymbolAddress((void**)&Ph,  g_Ph);
    cudaGetSymbolAddress((void**)&RS,  g_RS);
    cudaGetSymbolAddress((void**)&X,   g_X);
    cudaGetSymbolAddress((void**)&W,   g_W);
    cudaGetSymbolAddress((void**)&Bc,  g_B);

    const size_t SHM = 3 * STG + 1024;           // 99,328 B
    static bool attr_set = false;
    if (!attr_set){
        cudaFuncSetAttribute(gemm_h, cudaFuncAttributeMaxDynamicSharedMemorySize, (int)SHM);
        attr_set = true;
    }

    const long SD = (long)SEQ * DIM;
    const long SS = (long)SEQ * SEQ;
    const int  DD = DIM * DIM;
    const int  LQKV = 3 * DIM;
    dim3 t(256);

    to_half<<<(MTOT*DIM/4 + 255)/256, 256>>>(x,  X,        MTOT*DIM/4);
    to_half<<<(DD/4 + 255)/256, 256>>>(Wq, W,            DD/4);
    to_half<<<(DD/4 + 255)/256, 256>>>(Wk, W + DD,       DD/4);
    to_half<<<(DD/4 + 255)/256, 256>>>(Wv, W + 2*DD,     DD/4);
    prep_aux<<<(MTOT + 255)/256, 256>>>(bq, bk, bv, Bc, RS);

    // Fused QKV projection: [8192,3072] = X @ [Wq;Wk;Wv]^T + b -> fp16
    dim3 gq(LQKV / 128, MTOT / 128, 1);
    gemm_h<<<gq, t, SHM>>>(X, W, Bc, nullptr, QKV, DIM, DIM, DIM, LQKV,
                           0, 0, 0, 1.0f, 0);

    // VT[b][d][s] = V[b][s][d]
    transpose_sd<<<dim3(SEQ/32, DIM/32, BATCH), dim3(32, 8)>>>(QKV + 2*DIM, VT, LQKV);

    // Ph = exp(Q K^T / 32) masked + atomic row sums; lower-triangle blocks only
    dim3 gs(SEQ / 128, SEQ / 128, BATCH);
    gemm_h<<<gs, t, SHM>>>(QKV, QKV + DIM, nullptr, RS, Ph, DIM, LQKV, LQKV, SEQ,
                           (long)SEQ * LQKV, (long)SEQ * LQKV, SS, 0.03125f, 1);

    // out = (Ph @ V) / rowsum -> f32; K truncated at causal boundary
    dim3 go(DIM / 128, SEQ / 128, BATCH);
    gemm_h<<<go, t, SHM>>>(Ph, VT, nullptr, RS, out, SEQ, SEQ, SEQ, DIM,
                           SS, SD, SD, 1.0f, 2);
}

// round 14
// speedup vs baseline: 1.2988x; 1.0190x over previous
#include <cuda_runtime.h>
#include <cuda_fp16.h>
#include <cstdint>
#include <math.h>

#define BATCH 4
#define SEQ   2048
#define DIM   1024
#define MTOT  (BATCH*SEQ)

// Scratch (__device__ globals; allocation-free rule)
__device__ __half g_QKV[(size_t)MTOT*3*DIM];    // 48 MB ([8192][3072]: Q|K|V fp16)
__device__ __half g_VT [(size_t)BATCH*SEQ*DIM]; // 16 MB (V^T per batch: [D][S])
__device__ __half g_Ph [(size_t)BATCH*SEQ*SEQ]; // 32 MB (exp(scores) fp16, masked)
__device__ float  g_RS [MTOT];                  // row sums of exp(scores)
__device__ __half g_X  [(size_t)MTOT*DIM];      // 16 MB (x fp16)
__device__ __half g_W  [(size_t)3*DIM*DIM];     //  6 MB (Wq|Wk|Wv fp16, row-concat)
__device__ float  g_B  [3*DIM];                 // packed bias (f32)

// ---------------------------------------------------------------------------
__device__ __forceinline__ uint32_t smem_u32(const void* p){
    uint32_t a;
    asm("{ .reg .u64 t; cvta.to.shared.u64 t, %1; cvt.u32.u64 %0, t; }"
        : "=r"(a) : "l"(p));
    return a;
}
#define SW128(o) ((o) ^ (((o) >> 3) & 0x70))

__device__ __forceinline__ void cp16(uint32_t s, const void* g){
    asm volatile("cp.async.cg.shared.global [%0], [%1], 16;" :: "r"(s), "l"(g));
}

// ---------------------------------------------------------------------------
__global__ __launch_bounds__(256)
void to_half(const float* __restrict__ src, __half* __restrict__ dst, int n4)
{
    int i = blockIdx.x * 256 + threadIdx.x;
    if (i >= n4) return;
    float4 v = ((const float4*)src)[i];
    ((__half2*)dst)[i*2]   = __floats2half2_rn(v.x, v.y);
    ((__half2*)dst)[i*2+1] = __floats2half2_rn(v.z, v.w);
}

// pack bias + zero row sums, one launch (grid covers MTOT)
__global__ __launch_bounds__(256)
void prep_aux(const float* __restrict__ bq, const float* __restrict__ bk,
              const float* __restrict__ bv, float* __restrict__ b,
              float* __restrict__ rs)
{
    int i = blockIdx.x * 256 + threadIdx.x;
    if (i < DIM){ b[i] = bq[i]; b[DIM + i] = bk[i]; b[2*DIM + i] = bv[i]; }
    if (i < MTOT) rs[i] = 0.f;
}

// ---------------------------------------------------------------------------
// fp16 HMMA GEMM-NT, CTA tile 128x128, BK=64, 3-stage cp.async (2 in flight),
// one __syncthreads per chunk. 4 warps (2M x 2N), warp tile 64x64
// (square warp grid halves SMEM fragment re-read traffic vs 4x2/32x64).
// mode 0: C fp16 = acc + bias (QKV)
// mode 1: Ph fp16 = causal-masked __expf(acc*scale); atomic rowsum (skip bx>by)
// mode 2: C f32 = acc / rowsum[row]; K truncated at (by+1)*128
// ---------------------------------------------------------------------------
#define STG 32768u

__global__ __launch_bounds__(128, 2)
void gemm_h(const __half* __restrict__ A, const __half* __restrict__ B,
            const float* __restrict__ bias, float* __restrict__ rowsum,
            void* __restrict__ Cv,
            int K, int lda, int ldb, int ldc,
            long sA, long sB, long sC, float scale, int mode)
{
    const int bx = blockIdx.x, by = blockIdx.y, bz = blockIdx.z;
    if (mode == 1 && bx > by) return;
    A += (size_t)bz * sA; B += (size_t)bz * sB;

    const int Keff = (mode == 2) ? min(K, (by + 1) * 128) : K;
    const int nch  = Keff >> 6;

    extern __shared__ char dsm[];
    const uint32_t base = (smem_u32(dsm) + 1023) & ~1023u;
    const int tid = threadIdx.x, lane = tid & 31, wid = tid >> 5;
    const int wm = wid >> 1, wn = wid & 1;     // warp grid 2 (M) x 2 (N)

    const __half* Ab = A + (size_t)(by * 128) * lda;
    const __half* Bb = B + (size_t)(bx * 128) * ldb;

    // tile: 128 rows x 64 fp16 (128B rows), SW128, 16KB each (A then B)
    auto load_tile = [&](const __half* gb, int ld, int k0, uint32_t sbase){
        #pragma unroll
        for (int it = 0; it < 8; it++){
            int idx = tid + it * 128;
            int r = idx >> 3, c8 = idx & 7;
            uint32_t off = (uint32_t)(r * 128 + c8 * 16);
            cp16(sbase + SW128(off), gb + (size_t)r * ld + k0 + c8 * 8);
        }
    };

    // ldmatrix lane offsets (tile-relative, pre-swizzle)
    const uint32_t offA = (uint32_t)((wm*64 + (lane & 15)) * 128 + (lane >> 4) * 16);
    uint32_t offB[4];
    #pragma unroll
    for (int g = 0; g < 4; g++)
        offB[g] = (uint32_t)((wn*64 + g*16 + (lane & 7) + ((lane >> 4) & 1) * 8) * 128
                             + ((lane >> 3) & 1) * 16);

    float acc[4][8][4];
    #pragma unroll
    for (int mt = 0; mt < 4; mt++)
        #pragma unroll
        for (int nt = 0; nt < 8; nt++)
            #pragma unroll
            for (int j = 0; j < 4; j++) acc[mt][nt][j] = 0.f;

    // prologue: chunks 0,1 into stages 0,1 (2 in flight)
    load_tile(Ab, lda, 0, base);
    load_tile(Bb, ldb, 0, base + 16384);
    asm volatile("cp.async.commit_group;");
    if (nch > 1){
        load_tile(Ab, lda, 64, base + STG);
        load_tile(Bb, ldb, 64, base + STG + 16384);
    }
    asm volatile("cp.async.commit_group;");

    for (int i = 0; i < nch; i++){
        asm volatile("cp.async.wait_group 1;");
        __syncthreads();                         // chunk i ready; i-1 fully consumed
        {
            int s = i + 2;
            if (s < nch){
                uint32_t sb = base + (uint32_t)(s % 3) * STG;
                load_tile(Ab, lda, s * 64, sb);
                load_tile(Bb, ldb, s * 64, sb + 16384);
            }
            asm volatile("cp.async.commit_group;");
        }
        const uint32_t ab = base + (uint32_t)(i % 3) * STG;
        const uint32_t bb = ab + 16384;

        #pragma unroll
        for (int ks = 0; ks < 4; ks++){
            const uint32_t kadd = ks * 32;
            uint32_t ar[4][4];
            #pragma unroll
            for (int mt = 0; mt < 4; mt++){
                uint32_t ad = ab + SW128(offA + (uint32_t)mt * 2048 + kadd);
                asm volatile(
                    "ldmatrix.sync.aligned.m8n8.x4.shared.b16 {%0,%1,%2,%3}, [%4];"
                    : "=r"(ar[mt][0]), "=r"(ar[mt][1]),
                      "=r"(ar[mt][2]), "=r"(ar[mt][3]) : "r"(ad));
            }
            uint32_t br[8][2];
            #pragma unroll
            for (int g = 0; g < 4; g++){
                uint32_t ad = bb + SW128(offB[g] + kadd);
                asm volatile(
                    "ldmatrix.sync.aligned.m8n8.x4.shared.b16 {%0,%1,%2,%3}, [%4];"
                    : "=r"(br[2*g][0]), "=r"(br[2*g][1]),
                      "=r"(br[2*g+1][0]), "=r"(br[2*g+1][1]) : "r"(ad));
            }
            #pragma unroll
            for (int mt = 0; mt < 4; mt++)
                #pragma unroll
                for (int nt = 0; nt < 8; nt++){
                    asm volatile(
                        "mma.sync.aligned.m16n8k16.row.col.f32.f16.f16.f32 "
                        "{%0,%1,%2,%3}, {%4,%5,%6,%7}, {%8,%9}, {%0,%1,%2,%3};"
                        : "+f"(acc[mt][nt][0]), "+f"(acc[mt][nt][1]),
                          "+f"(acc[mt][nt][2]), "+f"(acc[mt][nt][3])
                        : "r"(ar[mt][0]), "r"(ar[mt][1]),
                          "r"(ar[mt][2]), "r"(ar[mt][3]),
                          "r"(br[nt][0]), "r"(br[nt][1]));
                }
        }
    }

    // ---------------- epilogue ----------------
    const int r0 = lane >> 2, c0 = (lane & 3) * 2;

    if (mode == 0){
        __half* C = (__half*)Cv + (size_t)bz * sC;
        #pragma unroll
        for (int mt = 0; mt < 4; mt++){
            const int mrow = by * 128 + wm * 64 + mt * 16 + r0;
            #pragma unroll
            for (int nt = 0; nt < 8; nt++){
                const int col = bx * 128 + wn * 64 + nt * 8 + c0;
                float b0 = bias[col], b1 = bias[col + 1];
                *(__half2*)(C + (size_t)mrow * ldc + col) =
                    __floats2half2_rn(acc[mt][nt][0] + b0, acc[mt][nt][1] + b1);
                *(__half2*)(C + (size_t)(mrow + 8) * ldc + col) =
                    __floats2half2_rn(acc[mt][nt][2] + b0, acc[mt][nt][3] + b1);
            }
        }
    } else if (mode == 1){
        __half* C = (__half*)Cv + (size_t)bz * sC;
        #pragma unroll
        for (int mt = 0; mt < 4; mt++){
            const int q0 = by * 128 + wm * 64 + mt * 16 + r0;
            const int q1 = q0 + 8;
            float rs0 = 0.f, rs1 = 0.f;
            #pragma unroll
            for (int nt = 0; nt < 8; nt++){
                const int col = bx * 128 + wn * 64 + nt * 8 + c0;
                float e0 = (col     <= q0) ? __expf(acc[mt][nt][0] * scale) : 0.f;
                float e1 = (col + 1 <= q0) ? __expf(acc[mt][nt][1] * scale) : 0.f;
                float e2 = (col     <= q1) ? __expf(acc[mt][nt][2] * scale) : 0.f;
                float e3 = (col + 1 <= q1) ? __expf(acc[mt][nt][3] * scale) : 0.f;
                rs0 += e0 + e1;
                rs1 += e2 + e3;
                *(__half2*)(C + (size_t)q0 * ldc + col) = __floats2half2_rn(e0, e1);
                *(__half2*)(C + (size_t)q1 * ldc + col) = __floats2half2_rn(e2, e3);
            }
            // reduce across the 4 lanes sharing each row
            rs0 += __shfl_xor_sync(0xffffffffu, rs0, 1);
            rs0 += __shfl_xor_sync(0xffffffffu, rs0, 2);
            rs1 += __shfl_xor_sync(0xffffffffu, rs1, 1);
            rs1 += __shfl_xor_sync(0xffffffffu, rs1, 2);
            if ((lane & 3) == 0){
                atomicAdd(rowsum + bz * SEQ + q0, rs0);
                atomicAdd(rowsum + bz * SEQ + q1, rs1);
            }
        }
    } else {
        float* C = (float*)Cv + (size_t)bz * sC;
        #pragma unroll
        for (int mt = 0; mt < 4; mt++){
            const int mrow = by * 128 + wm * 64 + mt * 16 + r0;
            const float i0 = 1.0f / rowsum[bz * SEQ + mrow];
            const float i1 = 1.0f / rowsum[bz * SEQ + mrow + 8];
            #pragma unroll
            for (int nt = 0; nt < 8; nt++){
                const int col = bx * 128 + wn * 64 + nt * 8 + c0;
                *(float2*)(C + (size_t)mrow * ldc + col) =
                    make_float2(acc[mt][nt][0] * i0, acc[mt][nt][1] * i0);
                *(float2*)(C + (size_t)(mrow + 8) * ldc + col) =
                    make_float2(acc[mt][nt][2] * i1, acc[mt][nt][3] * i1);
            }
        }
    }
}

// ---------------------------------------------------------------------------
__global__ __launch_bounds__(256)
void transpose_sd(const __half* __restrict__ V, __half* __restrict__ VT, int ldv)
{
    __shared__ __half t[32][33];
    const int b  = blockIdx.z;
    const int s0 = blockIdx.x * 32, d0 = blockIdx.y * 32;
    const __half* Vb = V  + (size_t)b * SEQ * ldv;
    __half* VTb      = VT + (size_t)b * SEQ * DIM;
    const int x = threadIdx.x, y = threadIdx.y;   // 32 x 8
    #pragma unroll
    for (int i = 0; i < 32; i += 8)
        t[y + i][x] = Vb[(size_t)(s0 + y + i) * ldv + d0 + x];
    __syncthreads();
    #pragma unroll
    for (int i = 0; i < 32; i += 8)
        VTb[(size_t)(d0 + y + i) * SEQ + s0 + x] = t[x][y + i];
}

// ---------------------------------------------------------------------------
extern "C" void kernel_launch(void* const* d_in, const int* in_sizes, int n_in,
                              void* d_out, int out_size)
{
    const float* x  = (const float*)d_in[0];
    const float* Wq = (const float*)d_in[1];
    const float* bq = (const float*)d_in[2];
    const float* Wk = (const float*)d_in[3];
    const float* bk = (const float*)d_in[4];
    const float* Wv = (const float*)d_in[5];
    const float* bv = (const float*)d_in[6];
    float* out = (float*)d_out;

    __half *QKV, *VT, *Ph, *X, *W;
    float *RS, *Bc;
    cudaGetSymbolAddress((void**)&QKV, g_QKV);
    cudaGetSymbolAddress((void**)&VT,  g_VT);
    cudaGetSymbolAddress((void**)&Ph,  g_Ph);
    cudaGetSymbolAddress((void**)&RS,  g_RS);
    cudaGetSymbolAddress((void**)&X,   g_X);
    cudaGetSymbolAddress((void**)&W,   g_W);
    cudaGetSymbolAddress((void**)&Bc,  g_B);

    const size_t SHM = 3 * STG + 1024;           // 99,328 B
    static bool attr_set = false;
    if (!attr_set){
        cudaFuncSetAttribute(gemm_h, cudaFuncAttributeMaxDynamicSharedMemorySize, (int)SHM);
        attr_set = true;
    }

    const long SD = (long)SEQ * DIM;
    const long SS = (long)SEQ * SEQ;
    const int  DD = DIM * DIM;
    const int  LQKV = 3 * DIM;
    dim3 t(128);

    to_half<<<(MTOT*DIM/4 + 255)/256, 256>>>(x,  X,        MTOT*DIM/4);
    to_half<<<(DD/4 + 255)/256, 256>>>(Wq, W,            DD/4);
    to_half<<<(DD/4 + 255)/256, 256>>>(Wk, W + DD,       DD/4);
    to_half<<<(DD/4 + 255)/256, 256>>>(Wv, W + 2*DD,     DD/4);
    prep_aux<<<(MTOT + 255)/256, 256>>>(bq, bk, bv, Bc, RS);

    // Fused QKV projection: [8192,3072] = X @ [Wq;Wk;Wv]^T + b -> fp16
    dim3 gq(LQKV / 128, MTOT / 128, 1);
    gemm_h<<<gq, t, SHM>>>(X, W, Bc, nullptr, QKV, DIM, DIM, DIM, LQKV,
                           0, 0, 0, 1.0f, 0);

    // VT[b][d][s] = V[b][s][d]
    transpose_sd<<<dim3(SEQ/32, DIM/32, BATCH), dim3(32, 8)>>>(QKV + 2*DIM, VT, LQKV);

    // Ph = exp(Q K^T / 32) masked + atomic row sums; lower-triangle blocks only
    dim3 gs(SEQ / 128, SEQ / 128, BATCH);
    gemm_h<<<gs, t, SHM>>>(QKV, QKV + DIM, nullptr, RS, Ph, DIM, LQKV, LQKV, SEQ,
                           (long)SEQ * LQKV, (long)SEQ * LQKV, SS, 0.03125f, 1);

    // out = (Ph @ V) / rowsum -> f32; K truncated at causal boundary
    dim3 go(DIM / 128, SEQ / 128, BATCH);
    gemm_h<<<go, t, SHM>>>(Ph, VT, nullptr, RS, out, SEQ, SEQ, SEQ, DIM,
                           SS, SD, SD, 1.0f, 2);
}

// round 15
// speedup vs baseline: 1.3087x; 1.0076x over previous
#include <cuda_runtime.h>
#include <cuda_fp16.h>
#include <cstdint>
#include <math.h>

#define BATCH 4
#define SEQ   2048
#define DIM   1024
#define MTOT  (BATCH*SEQ)

// Scratch (__device__ globals; allocation-free rule)
__device__ __half g_QKV[(size_t)MTOT*3*DIM];    // 48 MB ([8192][3072]: Q|K|V fp16)
__device__ __half g_VT [(size_t)BATCH*SEQ*DIM]; // 16 MB (V^T per batch: [D][S])
__device__ __half g_Ph [(size_t)BATCH*SEQ*SEQ]; // 32 MB (exp(scores) fp16, masked)
__device__ float  g_RS [MTOT];                  // row sums of exp(scores)
__device__ __half g_X  [(size_t)MTOT*DIM];      // 16 MB (x fp16)
__device__ __half g_W  [(size_t)3*DIM*DIM];     //  6 MB (Wq|Wk|Wv fp16, row-concat)
__device__ float  g_B  [3*DIM];                 // packed bias (f32)

// ---------------------------------------------------------------------------
__device__ __forceinline__ uint32_t smem_u32(const void* p){
    uint32_t a;
    asm("{ .reg .u64 t; cvta.to.shared.u64 t, %1; cvt.u32.u64 %0, t; }"
        : "=r"(a) : "l"(p));
    return a;
}
#define SW128(o) ((o) ^ (((o) >> 3) & 0x70))

__device__ __forceinline__ void cp16(uint32_t s, const void* g){
    asm volatile("cp.async.cg.shared.global [%0], [%1], 16;" :: "r"(s), "l"(g));
}

// ---------------------------------------------------------------------------
// One-shot prep: convert x -> X (fp16), Wq|Wk|Wv -> W (fp16), pack bias,
// zero row sums. Region-switched on blockIdx.x; 256 threads, float4 granularity.
//   blocks [0, 8192)        : x        (2,097,152 float4)
//   blocks [8192, 11264)    : weights  (3 x 1024 blocks of 262,144 float4 each)
//   blocks [11264, 11296)   : bias pack + RS zero (8192 threads)
// ---------------------------------------------------------------------------
__global__ __launch_bounds__(256)
void prep_all(const float* __restrict__ x,
              const float* __restrict__ Wq, const float* __restrict__ Wk,
              const float* __restrict__ Wv,
              const float* __restrict__ bq, const float* __restrict__ bk,
              const float* __restrict__ bv,
              __half* __restrict__ X, __half* __restrict__ W,
              float* __restrict__ b, float* __restrict__ rs)
{
    const int bid = blockIdx.x;
    if (bid < 8192){
        int i = bid * 256 + threadIdx.x;          // < 2,097,152
        float4 v = ((const float4*)x)[i];
        ((__half2*)X)[i*2]   = __floats2half2_rn(v.x, v.y);
        ((__half2*)X)[i*2+1] = __floats2half2_rn(v.z, v.w);
    } else if (bid < 11264){
        int rb = bid - 8192;
        int third = rb >> 10;                     // 0,1,2
        int i = (rb & 1023) * 256 + threadIdx.x;  // < 262,144
        const float* src = (third == 0) ? Wq : (third == 1) ? Wk : Wv;
        float4 v = ((const float4*)src)[i];
        __half2* dst = (__half2*)(W + (size_t)third * DIM * DIM);
        dst[i*2]   = __floats2half2_rn(v.x, v.y);
        dst[i*2+1] = __floats2half2_rn(v.z, v.w);
    } else {
        int i = (bid - 11264) * 256 + threadIdx.x;  // < 8192
        if (i < DIM){ b[i] = bq[i]; b[DIM + i] = bk[i]; b[2*DIM + i] = bv[i]; }
        rs[i] = 0.f;
    }
}

// ---------------------------------------------------------------------------
// fp16 HMMA GEMM-NT, CTA tile 128x128, BK=64, 3-stage cp.async (2 in flight),
// ONE __syncthreads per chunk. 8 warps (4M x 2N), warp tile 32x64.
// mode 0: C fp16 = acc + bias (QKV)
// mode 1: Ph fp16 = causal-masked __expf(acc*scale); atomic rowsum (skip bx>by)
// mode 2: C f32 = acc / rowsum[row]; K truncated at (by+1)*128
// ---------------------------------------------------------------------------
#define STG 32768u

__global__ __launch_bounds__(256, 2)
void gemm_h(const __half* __restrict__ A, const __half* __restrict__ B,
            const float* __restrict__ bias, float* __restrict__ rowsum,
            void* __restrict__ Cv,
            int K, int lda, int ldb, int ldc,
            long sA, long sB, long sC, float scale, int mode)
{
    const int bx = blockIdx.x, by = blockIdx.y, bz = blockIdx.z;
    if (mode == 1 && bx > by) return;
    A += (size_t)bz * sA; B += (size_t)bz * sB;

    const int Keff = (mode == 2) ? min(K, (by + 1) * 128) : K;
    const int nch  = Keff >> 6;

    extern __shared__ char dsm[];
    const uint32_t base = (smem_u32(dsm) + 1023) & ~1023u;
    const int tid = threadIdx.x, lane = tid & 31, wid = tid >> 5;
    const int wm = wid & 3, wn = wid >> 2;

    const __half* Ab = A + (size_t)(by * 128) * lda;
    const __half* Bb = B + (size_t)(bx * 128) * ldb;

    auto load_tile = [&](const __half* gb, int ld, int k0, uint32_t sbase){
        #pragma unroll
        for (int it = 0; it < 4; it++){
            int idx = tid + it * 256;
            int r = idx >> 3, c8 = idx & 7;
            uint32_t off = (uint32_t)(r * 128 + c8 * 16);
            cp16(sbase + SW128(off), gb + (size_t)r * ld + k0 + c8 * 8);
        }
    };

    const uint32_t offA = (uint32_t)((wm*32 + (lane & 15)) * 128 + (lane >> 4) * 16);
    uint32_t offB[4];
    #pragma unroll
    for (int g = 0; g < 4; g++)
        offB[g] = (uint32_t)((wn*64 + g*16 + (lane & 7) + ((lane >> 4) & 1) * 8) * 128
                             + ((lane >> 3) & 1) * 16);

    float acc[2][8][4];
    #pragma unroll
    for (int mt = 0; mt < 2; mt++)
        #pragma unroll
        for (int nt = 0; nt < 8; nt++)
            #pragma unroll
            for (int j = 0; j < 4; j++) acc[mt][nt][j] = 0.f;

    // prologue: chunks 0,1 into stages 0,1 (2 in flight)
    load_tile(Ab, lda, 0, base);
    load_tile(Bb, ldb, 0, base + 16384);
    asm volatile("cp.async.commit_group;");
    if (nch > 1){
        load_tile(Ab, lda, 64, base + STG);
        load_tile(Bb, ldb, 64, base + STG + 16384);
    }
    asm volatile("cp.async.commit_group;");

    for (int i = 0; i < nch; i++){
        asm volatile("cp.async.wait_group 1;");
        __syncthreads();
        {
            int s = i + 2;
            if (s < nch){
                uint32_t sb = base + (uint32_t)(s % 3) * STG;
                load_tile(Ab, lda, s * 64, sb);
                load_tile(Bb, ldb, s * 64, sb + 16384);
            }
            asm volatile("cp.async.commit_group;");
        }
        const uint32_t ab = base + (uint32_t)(i % 3) * STG;
        const uint32_t bb = ab + 16384;

        #pragma unroll
        for (int ks = 0; ks < 4; ks++){
            const uint32_t kadd = ks * 32;
            uint32_t ar[2][4];
            #pragma unroll
            for (int mt = 0; mt < 2; mt++){
                uint32_t ad = ab + SW128(offA + (uint32_t)mt * 2048 + kadd);
                asm volatile(
                    "ldmatrix.sync.aligned.m8n8.x4.shared.b16 {%0,%1,%2,%3}, [%4];"
                    : "=r"(ar[mt][0]), "=r"(ar[mt][1]),
                      "=r"(ar[mt][2]), "=r"(ar[mt][3]) : "r"(ad));
            }
            uint32_t br[8][2];
            #pragma unroll
            for (int g = 0; g < 4; g++){
                uint32_t ad = bb + SW128(offB[g] + kadd);
                asm volatile(
                    "ldmatrix.sync.aligned.m8n8.x4.shared.b16 {%0,%1,%2,%3}, [%4];"
                    : "=r"(br[2*g][0]), "=r"(br[2*g][1]),
                      "=r"(br[2*g+1][0]), "=r"(br[2*g+1][1]) : "r"(ad));
            }
            #pragma unroll
            for (int mt = 0; mt < 2; mt++)
                #pragma unroll
                for (int nt = 0; nt < 8; nt++){
                    asm volatile(
                        "mma.sync.aligned.m16n8k16.row.col.f32.f16.f16.f32 "
                        "{%0,%1,%2,%3}, {%4,%5,%6,%7}, {%8,%9}, {%0,%1,%2,%3};"
                        : "+f"(acc[mt][nt][0]), "+f"(acc[mt][nt][1]),
                          "+f"(acc[mt][nt][2]), "+f"(acc[mt][nt][3])
                        : "r"(ar[mt][0]), "r"(ar[mt][1]),
                          "r"(ar[mt][2]), "r"(ar[mt][3]),
                          "r"(br[nt][0]), "r"(br[nt][1]));
                }
        }
    }

    // ---------------- epilogue ----------------
    const int r0 = lane >> 2, c0 = (lane & 3) * 2;

    if (mode == 0){
        __half* C = (__half*)Cv + (size_t)bz * sC;
        #pragma unroll
        for (int mt = 0; mt < 2; mt++){
            const int mrow = by * 128 + wm * 32 + mt * 16 + r0;
            #pragma unroll
            for (int nt = 0; nt < 8; nt++){
                const int col = bx * 128 + wn * 64 + nt * 8 + c0;
                float b0 = bias[col], b1 = bias[col + 1];
                *(__half2*)(C + (size_t)mrow * ldc + col) =
                    __floats2half2_rn(acc[mt][nt][0] + b0, acc[mt][nt][1] + b1);
                *(__half2*)(C + (size_t)(mrow + 8) * ldc + col) =
                    __floats2half2_rn(acc[mt][nt][2] + b0, acc[mt][nt][3] + b1);
            }
        }
    } else if (mode == 1){
        __half* C = (__half*)Cv + (size_t)bz * sC;
        float rs[2][2] = {{0.f, 0.f}, {0.f, 0.f}};
        #pragma unroll
        for (int mt = 0; mt < 2; mt++){
            const int q0 = by * 128 + wm * 32 + mt * 16 + r0;
            const int q1 = q0 + 8;
            #pragma unroll
            for (int nt = 0; nt < 8; nt++){
                const int col = bx * 128 + wn * 64 + nt * 8 + c0;
                float e0 = (col     <= q0) ? __expf(acc[mt][nt][0] * scale) : 0.f;
                float e1 = (col + 1 <= q0) ? __expf(acc[mt][nt][1] * scale) : 0.f;
                float e2 = (col     <= q1) ? __expf(acc[mt][nt][2] * scale) : 0.f;
                float e3 = (col + 1 <= q1) ? __expf(acc[mt][nt][3] * scale) : 0.f;
                rs[mt][0] += e0 + e1;
                rs[mt][1] += e2 + e3;
                *(__half2*)(C + (size_t)q0 * ldc + col) = __floats2half2_rn(e0, e1);
                *(__half2*)(C + (size_t)q1 * ldc + col) = __floats2half2_rn(e2, e3);
            }
        }
        #pragma unroll
        for (int mt = 0; mt < 2; mt++)
            #pragma unroll
            for (int h = 0; h < 2; h++){
                float v = rs[mt][h];
                v += __shfl_xor_sync(0xffffffffu, v, 1);
                v += __shfl_xor_sync(0xffffffffu, v, 2);
                if ((lane & 3) == 0){
                    int q = by * 128 + wm * 32 + mt * 16 + r0 + h * 8;
                    atomicAdd(rowsum + bz * SEQ + q, v);
                }
            }
    } else {
        float* C = (float*)Cv + (size_t)bz * sC;
        #pragma unroll
        for (int mt = 0; mt < 2; mt++){
            const int mrow = by * 128 + wm * 32 + mt * 16 + r0;
            const float i0 = 1.0f / rowsum[bz * SEQ + mrow];
            const float i1 = 1.0f / rowsum[bz * SEQ + mrow + 8];
            #pragma unroll
            for (int nt = 0; nt < 8; nt++){
                const int col = bx * 128 + wn * 64 + nt * 8 + c0;
                *(float2*)(C + (size_t)mrow * ldc + col) =
                    make_float2(acc[mt][nt][0] * i0, acc[mt][nt][1] * i0);
                *(float2*)(C + (size_t)(mrow + 8) * ldc + col) =
                    make_float2(acc[mt][nt][2] * i1, acc[mt][nt][3] * i1);
            }
        }
    }
}

// ---------------------------------------------------------------------------
__global__ __launch_bounds__(256)
void transpose_sd(const __half* __restrict__ V, __half* __restrict__ VT, int ldv)
{
    __shared__ __half t[32][33];
    const int b  = blockIdx.z;
    const int s0 = blockIdx.x * 32, d0 = blockIdx.y * 32;
    const __half* Vb = V  + (size_t)b * SEQ * ldv;
    __half* VTb      = VT + (size_t)b * SEQ * DIM;
    const int x = threadIdx.x, y = threadIdx.y;   // 32 x 8
    #pragma unroll
    for (int i = 0; i < 32; i += 8)
        t[y + i][x] = Vb[(size_t)(s0 + y + i) * ldv + d0 + x];
    __syncthreads();
    #pragma unroll
    for (int i = 0; i < 32; i += 8)
        VTb[(size_t)(d0 + y + i) * SEQ + s0 + x] = t[x][y + i];
}

// ---------------------------------------------------------------------------
extern "C" void kernel_launch(void* const* d_in, const int* in_sizes, int n_in,
                              void* d_out, int out_size)
{
    const float* x  = (const float*)d_in[0];
    const float* Wq = (const float*)d_in[1];
    const float* bq = (const float*)d_in[2];
    const float* Wk = (const float*)d_in[3];
    const float* bk = (const float*)d_in[4];
    const float* Wv = (const float*)d_in[5];
    const float* bv = (const float*)d_in[6];
    float* out = (float*)d_out;

    __half *QKV, *VT, *Ph, *X, *W;
    float *RS, *Bc;
    cudaGetSymbolAddress((void**)&QKV, g_QKV);
    cudaGetSymbolAddress((void**)&VT,  g_VT);
    cudaGetSymbolAddress((void**)&Ph,  g_Ph);
    cudaGetSymbolAddress((void**)&RS,  g_RS);
    cudaGetSymbolAddress((void**)&X,   g_X);
    cudaGetSymbolAddress((void**)&W,   g_W);
    cudaGetSymbolAddress((void**)&Bc,  g_B);

    const size_t SHM = 3 * STG + 1024;           // 99,328 B
    static bool attr_set = false;
    if (!attr_set){
        cudaFuncSetAttribute(gemm_h, cudaFuncAttributeMaxDynamicSharedMemorySize, (int)SHM);
        attr_set = true;
    }

    const long SD = (long)SEQ * DIM;
    const long SS = (long)SEQ * SEQ;
    const int  LQKV = 3 * DIM;
    dim3 t(256);

    // single prep launch: converts + bias pack + RS zero
    prep_all<<<11296, 256>>>(x, Wq, Wk, Wv, bq, bk, bv, X, W, Bc, RS);

    // Fused QKV projection: [8192,3072] = X @ [Wq;Wk;Wv]^T + b -> fp16
    dim3 gq(LQKV / 128, MTOT / 128, 1);
    gemm_h<<<gq, t, SHM>>>(X, W, Bc, nullptr, QKV, DIM, DIM, DIM, LQKV,
                           0, 0, 0, 1.0f, 0);

    // VT[b][d][s] = V[b][s][d]
    transpose_sd<<<dim3(SEQ/32, DIM/32, BATCH), dim3(32, 8)>>>(QKV + 2*DIM, VT, LQKV);

    // Ph = exp(Q K^T / 32) masked + atomic row sums; lower-triangle blocks only
    dim3 gs(SEQ / 128, SEQ / 128, BATCH);
    gemm_h<<<gs, t, SHM>>>(QKV, QKV + DIM, nullptr, RS, Ph, DIM, LQKV, LQKV, SEQ,
                           (long)SEQ * LQKV, (long)SEQ * LQKV, SS, 0.03125f, 1);

    // out = (Ph @ V) / rowsum -> f32; K truncated at causal boundary
    dim3 go(DIM / 128, SEQ / 128, BATCH);
    gemm_h<<<go, t, SHM>>>(Ph, VT, nullptr, RS, out, SEQ, SEQ, SEQ, DIM,
                           SS, SD, SD, 1.0f, 2);
}

// round 17
// speedup vs baseline: 1.3192x; 1.0081x over previous
#include <cuda_runtime.h>
#include <cuda_fp16.h>
#include <cstdint>
#include <math.h>

#define BATCH 4
#define SEQ   2048
#define DIM   1024
#define MTOT  (BATCH*SEQ)

// Scratch (__device__ globals; allocation-free rule)
__device__ __half g_QKV[(size_t)MTOT*3*DIM];    // 48 MB ([8192][3072]: Q|K|V fp16)
__device__ __half g_VT [(size_t)BATCH*SEQ*DIM]; // 16 MB (V^T per batch: [D][S])
__device__ __half g_Ph [(size_t)BATCH*SEQ*SEQ]; // 32 MB (exp(scores) fp16, masked)
__device__ float  g_RS [MTOT];                  // row sums of exp(scores)
__device__ __half g_X  [(size_t)MTOT*DIM];      // 16 MB (x fp16)
__device__ __half g_W  [(size_t)3*DIM*DIM];     //  6 MB (Wq|Wk|Wv fp16, row-concat)
__device__ float  g_B  [3*DIM];                 // packed bias (f32)

// ---------------------------------------------------------------------------
__device__ __forceinline__ uint32_t smem_u32(const void* p){
    uint32_t a;
    asm("{ .reg .u64 t; cvta.to.shared.u64 t, %1; cvt.u32.u64 %0, t; }"
        : "=r"(a) : "l"(p));
    return a;
}
#define SW128(o) ((o) ^ (((o) >> 3) & 0x70))

__device__ __forceinline__ void cp16(uint32_t s, const void* g){
    asm volatile("cp.async.cg.shared.global [%0], [%1], 16;" :: "r"(s), "l"(g));
}

// ---------------------------------------------------------------------------
// One-shot prep: convert x -> X (fp16), Wq|Wk|Wv -> W (fp16), pack bias,
// zero row sums. Region-switched on blockIdx.x.
// ---------------------------------------------------------------------------
__global__ __launch_bounds__(256)
void prep_all(const float* __restrict__ x,
              const float* __restrict__ Wq, const float* __restrict__ Wk,
              const float* __restrict__ Wv,
              const float* __restrict__ bq, const float* __restrict__ bk,
              const float* __restrict__ bv,
              __half* __restrict__ X, __half* __restrict__ W,
              float* __restrict__ b, float* __restrict__ rs)
{
    const int bid = blockIdx.x;
    if (bid < 8192){
        int i = bid * 256 + threadIdx.x;
        float4 v = ((const float4*)x)[i];
        ((__half2*)X)[i*2]   = __floats2half2_rn(v.x, v.y);
        ((__half2*)X)[i*2+1] = __floats2half2_rn(v.z, v.w);
    } else if (bid < 11264){
        int rb = bid - 8192;
        int third = rb >> 10;
        int i = (rb & 1023) * 256 + threadIdx.x;
        const float* src = (third == 0) ? Wq : (third == 1) ? Wk : Wv;
        float4 v = ((const float4*)src)[i];
        __half2* dst = (__half2*)(W + (size_t)third * DIM * DIM);
        dst[i*2]   = __floats2half2_rn(v.x, v.y);
        dst[i*2+1] = __floats2half2_rn(v.z, v.w);
    } else {
        int i = (bid - 11264) * 256 + threadIdx.x;
        if (i < DIM){ b[i] = bq[i]; b[DIM + i] = bk[i]; b[2*DIM + i] = bv[i]; }
        rs[i] = 0.f;
    }
}

// ---------------------------------------------------------------------------
// fp16 HMMA GEMM-NT, CTA tile 128x128, BK=64, 3-stage cp.async (2 in flight),
// ONE __syncthreads per chunk. 8 warps (4M x 2N), warp tile 32x64.
// mode 0: C fp16 = acc + bias (QKV)
// mode 1: Ph fp16 = causal-masked __expf(acc*scale) + atomic rowsum.
//         grid.x = 136 lower-triangle tiles; (bx,by) decoded from blockIdx.x.
// mode 2: C f32 = acc / rowsum[row]; K truncated at (by+1)*128.
//         by = gridDim.y-1-blockIdx.y (heaviest tiles launch first).
// ---------------------------------------------------------------------------
#define STG 32768u

__global__ __launch_bounds__(256, 2)
void gemm_h(const __half* __restrict__ A, const __half* __restrict__ B,
            const float* __restrict__ bias, float* __restrict__ rowsum,
            void* __restrict__ Cv,
            int K, int lda, int ldb, int ldc,
            long sA, long sB, long sC, float scale, int mode)
{
    int bx, by;
    const int bz = blockIdx.z;
    if (mode == 1){
        // triangular decode: blockIdx.x in [0,136) -> (bx<=by)
        int t = blockIdx.x;
        by = (int)((sqrtf(8.f * (float)t + 1.f) - 1.f) * 0.5f);
        while ((by + 1) * (by + 2) / 2 <= t) by++;
        while (by * (by + 1) / 2 > t) by--;
        bx = t - by * (by + 1) / 2;
    } else if (mode == 2){
        bx = blockIdx.x;
        by = gridDim.y - 1 - blockIdx.y;        // heavy-K first
    } else {
        bx = blockIdx.x;
        by = blockIdx.y;
    }
    A += (size_t)bz * sA; B += (size_t)bz * sB;

    const int Keff = (mode == 2) ? min(K, (by + 1) * 128) : K;
    const int nch  = Keff >> 6;

    extern __shared__ char dsm[];
    const uint32_t base = (smem_u32(dsm) + 1023) & ~1023u;
    const int tid = threadIdx.x, lane = tid & 31, wid = tid >> 5;
    const int wm = wid & 3, wn = wid >> 2;

    const __half* Ab = A + (size_t)(by * 128) * lda;
    const __half* Bb = B + (size_t)(bx * 128) * ldb;

    auto load_tile = [&](const __half* gb, int ld, int k0, uint32_t sbase){
        #pragma unroll
        for (int it = 0; it < 4; it++){
            int idx = tid + it * 256;
            int r = idx >> 3, c8 = idx & 7;
            uint32_t off = (uint32_t)(r * 128 + c8 * 16);
            cp16(sbase + SW128(off), gb + (size_t)r * ld + k0 + c8 * 8);
        }
    };

    const uint32_t offA = (uint32_t)((wm*32 + (lane & 15)) * 128 + (lane >> 4) * 16);
    uint32_t offB[4];
    #pragma unroll
    for (int g = 0; g < 4; g++)
        offB[g] = (uint32_t)((wn*64 + g*16 + (lane & 7) + ((lane >> 4) & 1) * 8) * 128
                             + ((lane >> 3) & 1) * 16);

    float acc[2][8][4];
    #pragma unroll
    for (int mt = 0; mt < 2; mt++)
        #pragma unroll
        for (int nt = 0; nt < 8; nt++)
            #pragma unroll
            for (int j = 0; j < 4; j++) acc[mt][nt][j] = 0.f;

    // prologue: chunks 0,1 into stages 0,1 (2 in flight)
    load_tile(Ab, lda, 0, base);
    load_tile(Bb, ldb, 0, base + 16384);
    asm volatile("cp.async.commit_group;");
    if (nch > 1){
        load_tile(Ab, lda, 64, base + STG);
        load_tile(Bb, ldb, 64, base + STG + 16384);
    }
    asm volatile("cp.async.commit_group;");

    for (int i = 0; i < nch; i++){
        asm volatile("cp.async.wait_group 1;");
        __syncthreads();
        {
            int s = i + 2;
            if (s < nch){
                uint32_t sb = base + (uint32_t)(s % 3) * STG;
                load_tile(Ab, lda, s * 64, sb);
                load_tile(Bb, ldb, s * 64, sb + 16384);
            }
            asm volatile("cp.async.commit_group;");
        }
        const uint32_t ab = base + (uint32_t)(i % 3) * STG;
        const uint32_t bb = ab + 16384;

        #pragma unroll
        for (int ks = 0; ks < 4; ks++){
            const uint32_t kadd = ks * 32;
            uint32_t ar[2][4];
            #pragma unroll
            for (int mt = 0; mt < 2; mt++){
                uint32_t ad = ab + SW128(offA + (uint32_t)mt * 2048 + kadd);
                asm volatile(
                    "ldmatrix.sync.aligned.m8n8.x4.shared.b16 {%0,%1,%2,%3}, [%4];"
                    : "=r"(ar[mt][0]), "=r"(ar[mt][1]),
                      "=r"(ar[mt][2]), "=r"(ar[mt][3]) : "r"(ad));
            }
            uint32_t br[8][2];
            #pragma unroll
            for (int g = 0; g < 4; g++){
                uint32_t ad = bb + SW128(offB[g] + kadd);
                asm volatile(
                    "ldmatrix.sync.aligned.m8n8.x4.shared.b16 {%0,%1,%2,%3}, [%4];"
                    : "=r"(br[2*g][0]), "=r"(br[2*g][1]),
                      "=r"(br[2*g+1][0]), "=r"(br[2*g+1][1]) : "r"(ad));
            }
            #pragma unroll
            for (int mt = 0; mt < 2; mt++)
                #pragma unroll
                for (int nt = 0; nt < 8; nt++){
                    asm volatile(
                        "mma.sync.aligned.m16n8k16.row.col.f32.f16.f16.f32 "
                        "{%0,%1,%2,%3}, {%4,%5,%6,%7}, {%8,%9}, {%0,%1,%2,%3};"
                        : "+f"(acc[mt][nt][0]), "+f"(acc[mt][nt][1]),
                          "+f"(acc[mt][nt][2]), "+f"(acc[mt][nt][3])
                        : "r"(ar[mt][0]), "r"(ar[mt][1]),
                          "r"(ar[mt][2]), "r"(ar[mt][3]),
                          "r"(br[nt][0]), "r"(br[nt][1]));
                }
        }
    }

    // ---------------- epilogue ----------------
    const int r0 = lane >> 2, c0 = (lane & 3) * 2;

    if (mode == 0){
        __half* C = (__half*)Cv + (size_t)bz * sC;
        #pragma unroll
        for (int mt = 0; mt < 2; mt++){
            const int mrow = by * 128 + wm * 32 + mt * 16 + r0;
            #pragma unroll
            for (int nt = 0; nt < 8; nt++){
                const int col = bx * 128 + wn * 64 + nt * 8 + c0;
                float b0 = bias[col], b1 = bias[col + 1];
                *(__half2*)(C + (size_t)mrow * ldc + col) =
                    __floats2half2_rn(acc[mt][nt][0] + b0, acc[mt][nt][1] + b1);
                *(__half2*)(C + (size_t)(mrow + 8) * ldc + col) =
                    __floats2half2_rn(acc[mt][nt][2] + b0, acc[mt][nt][3] + b1);
            }
        }
    } else if (mode == 1){
        __half* C = (__half*)Cv + (size_t)bz * sC;
        float rs[2][2] = {{0.f, 0.f}, {0.f, 0.f}};
        #pragma unroll
        for (int mt = 0; mt < 2; mt++){
            const int q0 = by * 128 + wm * 32 + mt * 16 + r0;
            const int q1 = q0 + 8;
            #pragma unroll
            for (int nt = 0; nt < 8; nt++){
                const int col = bx * 128 + wn * 64 + nt * 8 + c0;
                float e0 = (col     <= q0) ? __expf(acc[mt][nt][0] * scale) : 0.f;
                float e1 = (col + 1 <= q0) ? __expf(acc[mt][nt][1] * scale) : 0.f;
                float e2 = (col     <= q1) ? __expf(acc[mt][nt][2] * scale) : 0.f;
                float e3 = (col + 1 <= q1) ? __expf(acc[mt][nt][3] * scale) : 0.f;
                rs[mt][0] += e0 + e1;
                rs[mt][1] += e2 + e3;
                *(__half2*)(C + (size_t)q0 * ldc + col) = __floats2half2_rn(e0, e1);
                *(__half2*)(C + (size_t)q1 * ldc + col) = __floats2half2_rn(e2, e3);
            }
        }
        #pragma unroll
        for (int mt = 0; mt < 2; mt++)
            #pragma unroll
            for (int h = 0; h < 2; h++){
                float v = rs[mt][h];
                v += __shfl_xor_sync(0xffffffffu, v, 1);
                v += __shfl_xor_sync(0xffffffffu, v, 2);
                if ((lane & 3) == 0){
                    int q = by * 128 + wm * 32 + mt * 16 + r0 + h * 8;
                    atomicAdd(rowsum + bz * SEQ + q, v);
                }
            }
    } else {
        float* C = (float*)Cv + (size_t)bz * sC;
        #pragma unroll
        for (int mt = 0; mt < 2; mt++){
            const int mrow = by * 128 + wm * 32 + mt * 16 + r0;
            const float i0 = 1.0f / rowsum[bz * SEQ + mrow];
            const float i1 = 1.0f / rowsum[bz * SEQ + mrow + 8];
            #pragma unroll
            for (int nt = 0; nt < 8; nt++){
                const int col = bx * 128 + wn * 64 + nt * 8 + c0;
                *(float2*)(C + (size_t)mrow * ldc + col) =
                    make_float2(acc[mt][nt][0] * i0, acc[mt][nt][1] * i0);
                *(float2*)(C + (size_t)(mrow + 8) * ldc + col) =
                    make_float2(acc[mt][nt][2] * i1, acc[mt][nt][3] * i1);
            }
        }
    }
}

// ---------------------------------------------------------------------------
__global__ __launch_bounds__(256)
void transpose_sd(const __half* __restrict__ V, __half* __restrict__ VT, int ldv)
{
    __shared__ __half t[32][33];
    const int b  = blockIdx.z;
    const int s0 = blockIdx.x * 32, d0 = blockIdx.y * 32;
    const __half* Vb = V  + (size_t)b * SEQ * ldv;
    __half* VTb      = VT + (size_t)b * SEQ * DIM;
    const int x = threadIdx.x, y = threadIdx.y;   // 32 x 8
    #pragma unroll
    for (int i = 0; i < 32; i += 8)
        t[y + i][x] = Vb[(size_t)(s0 + y + i) * ldv + d0 + x];
    __syncthreads();
    #pragma unroll
    for (int i = 0; i < 32; i += 8)
        VTb[(size_t)(d0 + y + i) * SEQ + s0 + x] = t[x][y + i];
}

// ---------------------------------------------------------------------------
extern "C" void kernel_launch(void* const* d_in, const int* in_sizes, int n_in,
                              void* d_out, int out_size)
{
    const float* x  = (const float*)d_in[0];
    const float* Wq = (const float*)d_in[1];
    const float* bq = (const float*)d_in[2];
    const float* Wk = (const float*)d_in[3];
    const float* bk = (const float*)d_in[4];
    const float* Wv = (const float*)d_in[5];
    const float* bv = (const float*)d_in[6];
    float* out = (float*)d_out;

    __half *QKV, *VT, *Ph, *X, *W;
    float *RS, *Bc;
    cudaGetSymbolAddress((void**)&QKV, g_QKV);
    cudaGetSymbolAddress((void**)&VT,  g_VT);
    cudaGetSymbolAddress((void**)&Ph,  g_Ph);
    cudaGetSymbolAddress((void**)&RS,  g_RS);
    cudaGetSymbolAddress((void**)&X,   g_X);
    cudaGetSymbolAddress((void**)&W,   g_W);
    cudaGetSymbolAddress((void**)&Bc,  g_B);

    const size_t SHM = 3 * STG + 1024;           // 99,328 B
    static bool attr_set = false;
    if (!attr_set){
        cudaFuncSetAttribute(gemm_h, cudaFuncAttributeMaxDynamicSharedMemorySize, (int)SHM);
        attr_set = true;
    }

    const long SD = (long)SEQ * DIM;
    const long SS = (long)SEQ * SEQ;
    const int  LQKV = 3 * DIM;
    dim3 t(256);

    // single prep launch: converts + bias pack + RS zero
    prep_all<<<11296, 256>>>(x, Wq, Wk, Wv, bq, bk, bv, X, W, Bc, RS);

    // Fused QKV projection: [8192,3072] = X @ [Wq;Wk;Wv]^T + b -> fp16
    dim3 gq(LQKV / 128, MTOT / 128, 1);
    gemm_h<<<gq, t, SHM>>>(X, W, Bc, nullptr, QKV, DIM, DIM, DIM, LQKV,
                           0, 0, 0, 1.0f, 0);

    // VT[b][d][s] = V[b][s][d]
    transpose_sd<<<dim3(SEQ/32, DIM/32, BATCH), dim3(32, 8)>>>(QKV + 2*DIM, VT, LQKV);

    // Ph = exp(Q K^T / 32) masked + atomic row sums; exact lower-triangle grid
    dim3 gs(136, 1, BATCH);
    gemm_h<<<gs, t, SHM>>>(QKV, QKV + DIM, nullptr, RS, Ph, DIM, LQKV, LQKV, SEQ,
                           (long)SEQ * LQKV, (long)SEQ * LQKV, SS, 0.03125f, 1);

    // out = (Ph @ V) / rowsum -> f32; heavy-K tiles launch first
    dim3 go(DIM / 128, SEQ / 128, BATCH);
    gemm_h<<<go, t, SHM>>>(Ph, VT, nullptr, RS, out, SEQ, SEQ, SEQ, DIM,
                           SS, SD, SD, 1.0f, 2);
}